// round 2
// baseline (speedup 1.0000x reference)
#include <cuda_runtime.h>
#include <cstdint>
#include <cstddef>

#define H 512
#define W 512
#define C 128
#define TI 16
#define TJ 16
#define HALO 23              // TI + 7 halo rows/cols
#define CHUNK 4260           // 23*23*8 = 4232 padded to 4260 (== 4 mod 32)
#define WJSTRIDE 1025        // odd stride for w3 j-dim: bank-spread staging
#define W3_FLOATS 16400      // 15*1025 + 63*16 + 15 = 16398, rounded to 16400 (16B align)
#define SMEM_FLOATS (W3_FLOATS + 8 * CHUNK + 529 + 256)
#define SMEM_BYTES (SMEM_FLOATS * 4)

typedef unsigned long long ull;

__device__ __forceinline__ ull pack2(float a, float b) {
    ull r; asm("mov.b64 %0, {%1, %2};" : "=l"(r) : "f"(a), "f"(b)); return r;
}
__device__ __forceinline__ void fma2(ull& d, ull a, ull b) {
    asm("fma.rn.f32x2 %0, %1, %2, %0;" : "+l"(d) : "l"(a), "l"(b));
}
__device__ __forceinline__ float2 unpack2(ull v) {
    float2 f; asm("mov.b64 {%0, %1}, %2;" : "=f"(f.x), "=f"(f.y) : "l"(v)); return f;
}

// Shared layout (floats):
//   w3  [16 j][64 t][16 i]  stride WJSTRIDE per j            (16400)
//   xs  [8 chg][CHUNK]  each chunk = [529 pix][8 ch]         (34080)
//   ch  [23*23] cnts halo                                    (529)
//   inv [256]  1/(att(cnts)+1e-6) per tile pixel             (256)
__global__ __launch_bounds__(128, 1) void cell_att_kernel(
    const float* __restrict__ gx,   // [H][W][C]
    const float* __restrict__ gw,   // [H][W][64]
    const float* __restrict__ gc,   // [H][W]
    float* __restrict__ gout)       // [H][W][C]
{
    extern __shared__ float smem[];
    float* w3  = smem;
    float* xs  = w3 + W3_FLOATS;
    float* ch  = xs + 8 * CHUNK;
    float* inv = ch + 529;

    const int tid = threadIdx.x;
    const int chg = tid & 7;          // channel group of 8 floats
    const int ig  = (tid >> 3) & 7;   // row group -> rows 2*ig, 2*ig+1
    const int jg  = tid >> 6;         // col group -> cols 8*jg..8*jg+7
    const int i0 = ig * 2, j0 = jg * 8;
    const int bi = blockIdx.y * TI, bj = blockIdx.x * TJ;

    // ---- stage weights, transposed to [j][t][i] (stride 1025 per j) ----
    #pragma unroll
    for (int rep = 0; rep < 2; ++rep) {
        int px = tid + rep * 128;           // 0..255 tile pixel
        int il = px >> 4, jl = px & 15;
        const float* src = gw + ((size_t)(bi + il) * W + (bj + jl)) * 64;
        float* dst = w3 + jl * WJSTRIDE + il;
        #pragma unroll
        for (int quad = 0; quad < 16; ++quad) {
            float4 v = *(const float4*)(src + quad * 4);
            int t0 = quad * 4;
            dst[(t0 + 0) * 16] = v.x;
            dst[(t0 + 1) * 16] = v.y;
            dst[(t0 + 2) * 16] = v.z;
            dst[(t0 + 3) * 16] = v.w;
        }
    }
    // ---- stage cnts halo (zero padded) ----
    for (int u = tid; u < 529; u += 128) {
        int hr = u / 23, hc = u % 23;
        int gr = bi + hr - 3, gcl = bj + hc - 3;
        float v = 0.f;
        if ((unsigned)gr < H && (unsigned)gcl < W) v = gc[(size_t)gr * W + gcl];
        ch[u] = v;
    }
    __syncthreads();

    // ---- per-pixel normalizer: inv = 1/(att(cnts) + 1e-6) ----
    #pragma unroll
    for (int rep = 0; rep < 2; ++rep) {
        int px = tid + rep * 128;
        int il = px >> 4, jl = px & 15;
        float s = 0.f;
        #pragma unroll
        for (int p = 0; p < 8; ++p)
            #pragma unroll
            for (int q = 0; q < 8; ++q)
                s += ch[(il + p) * 23 + (jl + q)] *
                     w3[jl * WJSTRIDE + (p * 8 + q) * 16 + il];
        inv[px] = 1.0f / (s + 1e-6f);
    }

    for (int pass = 0; pass < 2; ++pass) {
        __syncthreads();   // inv writes done / previous pass compute done
        const int cbase = pass * 64;

        // ---- stage 64-channel x halo into xs[chg][pix][8] ----
        for (int u = tid; u < 529 * 16; u += 128) {
            int pix = u >> 4, quad = u & 15;
            int hr = pix / 23, hc = pix % 23;
            int gr = bi + hr - 3, gcl = bj + hc - 3;
            float4 v = make_float4(0.f, 0.f, 0.f, 0.f);
            if ((unsigned)gr < H && (unsigned)gcl < W)
                v = *(const float4*)(gx + (((size_t)gr * W + gcl) * C + cbase + quad * 4));
            int cg2 = quad >> 1, half = quad & 1;
            *(float4*)(xs + cg2 * CHUNK + pix * 8 + half * 4) = v;
        }
        __syncthreads();

        // ---- compute: 2 rows x 8 cols x 8 channels per thread ----
        ull acc[2][8][4];
        #pragma unroll
        for (int a = 0; a < 2; ++a)
            #pragma unroll
            for (int b = 0; b < 8; ++b)
                #pragma unroll
                for (int k = 0; k < 4; ++k) acc[a][b][k] = 0ull;

        const float* xbase = xs + chg * CHUNK + ((i0 * 23 + j0) * 8);
        const float* wb0   = w3 + j0 * WJSTRIDE + i0;

        #pragma unroll
        for (int xr = 0; xr < 9; ++xr) {          // halo row i0+xr
            #pragma unroll
            for (int jj = 0; jj < 15; ++jj) {     // halo col j0+jj
                const ulonglong2* xp = (const ulonglong2*)(xbase + (xr * 23 + jj) * 8);
                ulonglong2 xa = xp[0];
                ulonglong2 xb = xp[1];
                ull xv0 = xa.x, xv1 = xa.y, xv2 = xb.x, xv3 = xb.y;
                #pragma unroll
                for (int di = 0; di < 2; ++di) {
                    const int p = xr - di;
                    if (p < 0 || p > 7) continue;     // compile-time
                    #pragma unroll
                    for (int j = 0; j < 8; ++j) {
                        const int q = jj - j;
                        if (q < 0 || q > 7) continue; // compile-time
                        float w = wb0[j * WJSTRIDE + (p * 8 + q) * 16 + di];
                        ull wp = pack2(w, w);
                        fma2(acc[di][j][0], xv0, wp);
                        fma2(acc[di][j][1], xv1, wp);
                        fma2(acc[di][j][2], xv2, wp);
                        fma2(acc[di][j][3], xv3, wp);
                    }
                }
            }
        }

        // ---- normalize + store ----
        #pragma unroll
        for (int di = 0; di < 2; ++di) {
            #pragma unroll
            for (int j = 0; j < 8; ++j) {
                const int li = i0 + di, lj = j0 + j;
                float s = inv[li * 16 + lj];
                float* op = gout + (((size_t)(bi + li) * W + (bj + lj)) * C + cbase + chg * 8);
                float2 a0 = unpack2(acc[di][j][0]);
                float2 a1 = unpack2(acc[di][j][1]);
                float2 a2 = unpack2(acc[di][j][2]);
                float2 a3 = unpack2(acc[di][j][3]);
                float4 v0 = make_float4(a0.x * s, a0.y * s, a1.x * s, a1.y * s);
                float4 v1 = make_float4(a2.x * s, a2.y * s, a3.x * s, a3.y * s);
                *(float4*)(op) = v0;
                *(float4*)(op + 4) = v1;
            }
        }
    }
}

extern "C" void kernel_launch(void* const* d_in, const int* in_sizes, int n_in,
                              void* d_out, int out_size) {
    const float* x0 = (const float*)d_in[0];
    const float* w  = (const float*)d_in[1];
    const float* c  = (const float*)d_in[2];
    float* out      = (float*)d_out;
    cudaFuncSetAttribute(cell_att_kernel,
                         cudaFuncAttributeMaxDynamicSharedMemorySize, SMEM_BYTES);
    dim3 grid(W / TJ, H / TI);
    cell_att_kernel<<<grid, 128, SMEM_BYTES>>>(x0, w, c, out);
}

// round 3
// speedup vs baseline: 1.7118x; 1.7118x over previous
#include <cuda_runtime.h>
#include <cstdint>
#include <cstddef>

#define H 512
#define W 512
#define C 128
#define TI 16
#define TJ 16
// weights smem: [16 i][16 j][64 t], i-stride padded 1024 -> 1032 (== 8 mod 32)
#define WISTRIDE 1032
#define W3_FLOATS (16 * WISTRIDE)        // 16512
// x halo smem per pass: 32 channels as [8 chg][529 pix][4 ch]
#define XCHUNK 2116                      // 529*4; 2116 mod 32 == 4 (bank spread)
#define XBUF (8 * XCHUNK)                // 16928 floats per buffer
#define SMEM_FLOATS (W3_FLOATS + 2 * XBUF + 529 + 256)
#define SMEM_BYTES (SMEM_FLOATS * 4)     // 204,612 B

typedef unsigned long long ull;

__device__ __forceinline__ ull pack2(float a, float b) {
    ull r; asm("mov.b64 %0, {%1, %2};" : "=l"(r) : "f"(a), "f"(b)); return r;
}
__device__ __forceinline__ void fma2(ull& d, ull a, ull b) {
    asm("fma.rn.f32x2 %0, %1, %2, %0;" : "+l"(d) : "l"(a), "l"(b));
}
__device__ __forceinline__ float2 unpack2(ull v) {
    float2 f; asm("mov.b64 {%0, %1}, %2;" : "=f"(f.x), "=f"(f.y) : "l"(v)); return f;
}
__device__ __forceinline__ void cp_async16(float* smem_dst, const float* gsrc, bool pred) {
    uint32_t s = (uint32_t)__cvta_generic_to_shared(smem_dst);
    int sz = pred ? 16 : 0;
    asm volatile("cp.async.cg.shared.global [%0], [%1], 16, %2;\n"
                 :: "r"(s), "l"(gsrc), "r"(sz));
}
__device__ __forceinline__ void cp_async4(float* smem_dst, const float* gsrc, bool pred) {
    uint32_t s = (uint32_t)__cvta_generic_to_shared(smem_dst);
    int sz = pred ? 4 : 0;
    asm volatile("cp.async.ca.shared.global [%0], [%1], 4, %2;\n"
                 :: "r"(s), "l"(gsrc), "r"(sz));
}
__device__ __forceinline__ void cp_commit() {
    asm volatile("cp.async.commit_group;\n" ::: "memory");
}
template <int N> __device__ __forceinline__ void cp_wait() {
    asm volatile("cp.async.wait_group %0;\n" :: "n"(N) : "memory");
}

// ---- stage one 32-channel x halo pass into xbuf[8 chg][529 pix][4] ----
__device__ __forceinline__ void stage_x(float* xbuf, const float* __restrict__ gx,
                                        int bi, int bj, int pass, int tid) {
    const int cbase = pass * 32;
    #pragma unroll 4
    for (int u = tid; u < 529 * 8; u += 256) {
        int q = u & 7, pix = u >> 3;
        int hr = pix / 23, hc = pix - hr * 23;
        int gr = bi + hr - 3, gcl = bj + hc - 3;
        bool ok = ((unsigned)gr < H) && ((unsigned)gcl < W);
        const float* src = ok
            ? gx + (((size_t)gr * W + gcl) * C + cbase + q * 4)
            : gx;
        cp_async16(xbuf + q * XCHUNK + pix * 4, src, ok);
    }
}

// ---- compute one pass: 1 row x 8 cols x 4 ch per thread ----
__device__ __forceinline__ void compute_pass(const float* __restrict__ xbuf,
                                             const float* __restrict__ w3,
                                             const float* __restrict__ inv,
                                             float* __restrict__ gout,
                                             int bi, int bj, int cbase,
                                             int row, int j0, int chg) {
    ull acc[8][2];
    #pragma unroll
    for (int j = 0; j < 8; ++j) { acc[j][0] = 0ull; acc[j][1] = 0ull; }

    const float* xb   = xbuf + chg * XCHUNK;
    const float* wrow = w3 + row * WISTRIDE + j0 * 64;

    #pragma unroll
    for (int p = 0; p < 8; ++p) {
        // load the 15-position halo row (4 ch each) into registers
        ull xv[15][2];
        const float* xr = xb + ((row + p) * 23 + j0) * 4;
        #pragma unroll
        for (int t = 0; t < 15; ++t) {
            ulonglong2 v = *(const ulonglong2*)(xr + t * 4);
            xv[t][0] = v.x; xv[t][1] = v.y;
        }
        #pragma unroll
        for (int j = 0; j < 8; ++j) {
            #pragma unroll
            for (int qg = 0; qg < 2; ++qg) {
                float4 w4 = *(const float4*)(wrow + j * 64 + p * 8 + qg * 4);
                ull w0 = pack2(w4.x, w4.x);
                ull w1 = pack2(w4.y, w4.y);
                ull w2 = pack2(w4.z, w4.z);
                ull w3p = pack2(w4.w, w4.w);
                const int q0 = qg * 4;
                fma2(acc[j][0], xv[j + q0 + 0][0], w0);
                fma2(acc[j][1], xv[j + q0 + 0][1], w0);
                fma2(acc[j][0], xv[j + q0 + 1][0], w1);
                fma2(acc[j][1], xv[j + q0 + 1][1], w1);
                fma2(acc[j][0], xv[j + q0 + 2][0], w2);
                fma2(acc[j][1], xv[j + q0 + 2][1], w2);
                fma2(acc[j][0], xv[j + q0 + 3][0], w3p);
                fma2(acc[j][1], xv[j + q0 + 3][1], w3p);
            }
        }
    }
    // normalize + store (128B coalesced across chg lanes)
    #pragma unroll
    for (int j = 0; j < 8; ++j) {
        float s = inv[row * 16 + j0 + j];
        float2 a0 = unpack2(acc[j][0]);
        float2 a1 = unpack2(acc[j][1]);
        float4 v = make_float4(a0.x * s, a0.y * s, a1.x * s, a1.y * s);
        *(float4*)(gout + (((size_t)(bi + row) * W + (bj + j0 + j)) * C
                           + cbase + chg * 4)) = v;
    }
}

__global__ __launch_bounds__(256, 1) void cell_att_kernel(
    const float* __restrict__ gx,   // [H][W][C]
    const float* __restrict__ gw,   // [H][W][64]
    const float* __restrict__ gc,   // [H][W]
    float* __restrict__ gout)       // [H][W][C]
{
    extern __shared__ float smem[];
    float* w3  = smem;                 // [16 i][16 j][64 t], i-stride 1032
    float* xs0 = w3 + W3_FLOATS;
    float* xs1 = xs0 + XBUF;
    float* ch  = xs1 + XBUF;           // 23x23 cnts halo
    float* inv = ch + 529;             // 256 per-pixel 1/(tcnt+1e-6)

    const int tid = threadIdx.x;
    const int chg = tid & 7;           // channel quad within pass (4 ch)
    const int rg  = (tid >> 3) & 3;
    const int wid = tid >> 5;
    const int jg  = wid & 1;
    const int row = rg + ((wid >> 1) << 2);   // 0..15
    const int j0  = jg * 8;
    const int bi = blockIdx.y * TI, bj = blockIdx.x * TJ;

    // ---- G0: weights (coalesced, natural layout) + cnts halo ----
    #pragma unroll 4
    for (int u = tid; u < 256 * 16; u += 256) {
        int quad = u & 15, px = u >> 4;
        int il = px >> 4, jl = px & 15;
        const float* src = gw + ((size_t)(bi + il) * W + (bj + jl)) * 64 + quad * 4;
        cp_async16(w3 + il * WISTRIDE + jl * 64 + quad * 4, src, true);
    }
    for (int u = tid; u < 529; u += 256) {
        int hr = u / 23, hc = u - hr * 23;
        int gr = bi + hr - 3, gcl = bj + hc - 3;
        bool ok = ((unsigned)gr < H) && ((unsigned)gcl < W);
        const float* src = ok ? gc + (size_t)gr * W + gcl : gc;
        cp_async4(ch + u, src, ok);
    }
    cp_commit();                       // G0
    stage_x(xs0, gx, bi, bj, 0, tid);
    cp_commit();                       // G1
    stage_x(xs1, gx, bi, bj, 1, tid);
    cp_commit();                       // G2

    cp_wait<2>();                      // G0 (weights + cnts) done
    __syncthreads();

    // ---- normalizer: inv = 1/(att(cnts)+1e-6), one pixel per thread ----
    {
        int il = tid >> 4, jl = tid & 15;
        const float* wpx = w3 + il * WISTRIDE + jl * 64;
        float s = 0.f;
        #pragma unroll
        for (int p = 0; p < 8; ++p)
            #pragma unroll
            for (int q = 0; q < 8; ++q)
                s += ch[(il + p) * 23 + (jl + q)] * wpx[p * 8 + q];
        inv[tid] = 1.0f / (s + 1e-6f);
    }

    cp_wait<1>();                      // G1 (x pass0) done
    __syncthreads();                   // inv + x0 visible to all
    compute_pass(xs0, w3, inv, gout, bi, bj, 0, row, j0, chg);

    __syncthreads();                   // all readers done with xs0
    stage_x(xs0, gx, bi, bj, 2, tid);
    cp_commit();                       // G3
    cp_wait<1>();                      // G2 (x pass1) done
    __syncthreads();
    compute_pass(xs1, w3, inv, gout, bi, bj, 32, row, j0, chg);

    __syncthreads();                   // all readers done with xs1
    stage_x(xs1, gx, bi, bj, 3, tid);
    cp_commit();                       // G4
    cp_wait<1>();                      // G3 (x pass2) done
    __syncthreads();
    compute_pass(xs0, w3, inv, gout, bi, bj, 64, row, j0, chg);

    cp_wait<0>();                      // G4 (x pass3) done
    __syncthreads();
    compute_pass(xs1, w3, inv, gout, bi, bj, 96, row, j0, chg);
}

extern "C" void kernel_launch(void* const* d_in, const int* in_sizes, int n_in,
                              void* d_out, int out_size) {
    const float* x0 = (const float*)d_in[0];
    const float* w  = (const float*)d_in[1];
    const float* c  = (const float*)d_in[2];
    float* out      = (float*)d_out;
    cudaFuncSetAttribute(cell_att_kernel,
                         cudaFuncAttributeMaxDynamicSharedMemorySize, SMEM_BYTES);
    dim3 grid(W / TJ, H / TI);
    cell_att_kernel<<<grid, 256, SMEM_BYTES>>>(x0, w, c, out);
}